// round 9
// baseline (speedup 1.0000x reference)
#include <cuda_runtime.h>

#define MAXN 100000
#define MAXE 1600000
#define NEG 0.2f

typedef unsigned long long ull;

// ---------------- scratch (static device globals; no allocation) -------------
__device__ float g_h0 [MAXN * 16];    // relu(x@W0)
__device__ float g_hl [MAXN * 96];    // source transform (current layer)
__device__ float g_hr [MAXN * 96];    // target transform (current layer)
__device__ float g_acc[MAXN * 96];    // layer-1 accumulator = skip + b1 + msgs
__device__ float g_wt [3 * 96 * 96];  // layer-2 weights transposed [mat][c][k]
__device__ int   g_src[MAXE];
__device__ int   g_dst[MAXE];
__device__ int   g_ssrc[MAXE];        // src ids sorted by dst (CSR payload)
__device__ int   g_cnt[MAXN];         // in-degree histogram
__device__ int   g_rs [MAXN + 1];     // CSR row starts
__device__ int   g_cur[MAXN];         // scatter cursors
__device__ int   g_bsum[128];
__device__ int   g_boff[128];
__device__ int   g_is64;

// ---------------- asm helpers -------------------------------------------------
__device__ __forceinline__ void ffma2(ull& acc, ull a, ull b) {
    asm("fma.rn.f32x2 %0, %1, %2, %0;" : "+l"(acc) : "l"(a), "l"(b));
}
__device__ __forceinline__ ull pack2(float x, float y) {
    ull r; asm("mov.b64 %0, {%1, %2};" : "=l"(r) : "f"(x), "f"(y)); return r;
}
__device__ __forceinline__ float2 unpack2(ull v) {
    float2 r; asm("mov.b64 {%0, %1}, %2;" : "=f"(r.x), "=f"(r.y) : "l"(v)); return r;
}
__device__ __forceinline__ float ex2(float v) {
    float r; asm("ex2.approx.ftz.f32 %0, %1;" : "=f"(r) : "f"(v)); return r;
}

// ---------------- init: zero histogram + dtype detect -------------------------
// Detect int64 vs int32 edge_index: node ids < 2^17, so int64 => odd words 0.
__global__ void k_init(const int* __restrict__ p, int n) {
    int i = blockIdx.x * blockDim.x + threadIdx.x;
    if (i < n) g_cnt[i] = 0;
    if (i == 0) {
        int acc = 0;
#pragma unroll
        for (int j = 1; j < 64; j += 2) acc |= p[j];
        g_is64 = (acc == 0) ? 1 : 0;
    }
}

// transpose layer-2 weights: g_wt[m*9216 + c*96 + k] = W[k*96 + c]
__global__ void k_wt(const float* __restrict__ Wl, const float* __restrict__ Wr,
                     const float* __restrict__ Wo) {
    int i = blockIdx.x * blockDim.x + threadIdx.x;
    if (i >= 9216) return;
    int c = i / 96, k = i % 96;
    float a = Wl[k * 96 + c], b = Wr[k * 96 + c], d = Wo[k * 96 + c];
    g_wt[i] = a;
    g_wt[9216 + i] = b;
    g_wt[2 * 9216 + i] = d;
}

__global__ void k_edges(const void* __restrict__ ei, int E) {
    int i = blockIdx.x * blockDim.x + threadIdx.x;
    if (i >= E) return;
    int s, d;
    if (g_is64) {
        const long long* p = (const long long*)ei;
        s = (int)p[i]; d = (int)p[E + i];
    } else {
        const int* p = (const int*)ei;
        s = p[i]; d = p[E + i];
    }
    g_src[i] = s;
    g_dst[i] = d;
    atomicAdd(&g_cnt[d], 1);
}

// ---------------- scan (3-kernel exclusive prefix sum over g_cnt) ------------

__global__ void k_scan1(int n) {
    __shared__ int tmp[1024];
    int tid = threadIdx.x;
    int i = blockIdx.x * 1024 + tid;
    int v = (i < n) ? g_cnt[i] : 0;
    tmp[tid] = v;
    __syncthreads();
#pragma unroll
    for (int o = 1; o < 1024; o <<= 1) {
        int t = (tid >= o) ? tmp[tid - o] : 0;
        __syncthreads();
        tmp[tid] += t;
        __syncthreads();
    }
    if (i < n) g_rs[i] = tmp[tid] - v;         // block-local exclusive
    if (tid == 1023) g_bsum[blockIdx.x] = tmp[tid];
}

__global__ void k_scan2(int nb) {
    __shared__ int tmp[128];
    int tid = threadIdx.x;
    int v = (tid < nb) ? g_bsum[tid] : 0;
    tmp[tid] = v;
    __syncthreads();
#pragma unroll
    for (int o = 1; o < 128; o <<= 1) {
        int t = (tid >= o) ? tmp[tid - o] : 0;
        __syncthreads();
        tmp[tid] += t;
        __syncthreads();
    }
    if (tid < nb) g_boff[tid] = tmp[tid] - v;  // exclusive block offsets
}

__global__ void k_scan3(int n, int E) {
    int i = blockIdx.x * blockDim.x + threadIdx.x;
    if (i < n) {
        int r = g_rs[i] + g_boff[i >> 10];
        g_rs[i] = r;
        g_cur[i] = r;
    }
    if (i == 0) g_rs[n] = E;
}

__global__ void k_scatter(int E) {
    int i = blockIdx.x * blockDim.x + threadIdx.x;
    if (i >= E) return;
    int d = g_dst[i];
    int pos = atomicAdd(&g_cur[d], 1);
    g_ssrc[pos] = g_src[i];
}

// ---------------- node transforms --------------------------------------------

// h0 = relu(x @ W0) : [n,128]@[128,16]. Shared-staged, float4 global loads.
__global__ void __launch_bounds__(256)
k_lin0(const float* __restrict__ x, const float* __restrict__ W0, int n) {
    __shared__ float sx[16 * 128];   // 16 rows of x
    __shared__ float sw[128 * 16];   // W0
    int tid = threadIdx.x;
    int row0 = blockIdx.x * 16;
    for (int i = tid; i < 512; i += 256)
        ((float4*)sw)[i] = ((const float4*)W0)[i];
    for (int i = tid; i < 512; i += 256) {
        int r = i >> 5;                // row within tile
        int row = row0 + r;
        float4 v = make_float4(0.f, 0.f, 0.f, 0.f);
        if (row < n) v = ((const float4*)x)[row * 32 + (i & 31)];
        ((float4*)sx)[i] = v;
    }
    __syncthreads();
    int r = tid >> 4, c = tid & 15;
    const float4* sxr = (const float4*)(sx + r * 128);
    float acc = 0.f;
#pragma unroll
    for (int k4 = 0; k4 < 32; k4++) {
        float4 h = sxr[k4];
        acc = fmaf(h.x, sw[(4 * k4 + 0) * 16 + c], acc);
        acc = fmaf(h.y, sw[(4 * k4 + 1) * 16 + c], acc);
        acc = fmaf(h.z, sw[(4 * k4 + 2) * 16 + c], acc);
        acc = fmaf(h.w, sw[(4 * k4 + 3) * 16 + c], acc);
    }
    int row = row0 + r;
    if (row < n) g_h0[row * 16 + c] = fmaxf(acc, 0.f);
}

// layer-1 transforms: weights in registers (one output column per thread),
// h rows staged in shared (broadcast reads). 64 rows per block.
__global__ void __launch_bounds__(384)
k_node1(const float* __restrict__ Wl, const float* __restrict__ bl,
        const float* __restrict__ Wr, const float* __restrict__ br,
        const float* __restrict__ Wf, const float* __restrict__ bf,
        const float* __restrict__ b1, int n) {
    __shared__ float sh[64 * 16];
    int c = threadIdx.x, ty = threadIdx.y;
    int tid = ty * 96 + c;
    int row0 = blockIdx.x * 64;
    float wl[16], wr[16], wf[16];
#pragma unroll
    for (int k = 0; k < 16; k++) {
        wl[k] = Wl[k * 96 + c];
        wr[k] = Wr[k * 96 + c];
        wf[k] = Wf[k * 96 + c];
    }
    float cbl = bl[c], cbr = br[c], cbf = bf[c] + b1[c];
    for (int i = tid; i < 1024; i += 384) {
        int r = i >> 4, k = i & 15;
        int row = row0 + r;
        sh[i] = (row < n) ? g_h0[row * 16 + k] : 0.f;
    }
    __syncthreads();
    for (int r = ty; r < 64; r += 4) {
        int row = row0 + r;
        if (row >= n) continue;
        float a0 = cbl, a1 = cbr, a2 = cbf;
#pragma unroll
        for (int k = 0; k < 16; k++) {
            float h = sh[r * 16 + k];
            a0 = fmaf(h, wl[k], a0);
            a1 = fmaf(h, wr[k], a1);
            a2 = fmaf(h, wf[k], a2);
        }
        g_hl[row * 96 + c] = a0;
        g_hr[row * 96 + c] = a1;
        g_acc[row * 96 + c] = a2;
    }
}

// layer-2 transforms via packed f32x2 FMA (FFMA2), weights from the
// TRANSPOSED copy g_wt so each chunk's 48 weights come in as 12 LDG.128.
// sh is transposed [k][r] stride 34 (aligned LDS.64, conflict-free).
__global__ void __launch_bounds__(384, 1)
k_node2(const float* __restrict__ bl, const float* __restrict__ br,
        const float* __restrict__ bo, const float* __restrict__ b2,
        float* __restrict__ out, int n) {
    __shared__ float sh[16 * 34];
    int c = threadIdx.x, ty = threadIdx.y;
    int tid = ty * 96 + c;
    int row0 = blockIdx.x * 32;
    ull a0[4], a1[4], a2[4];
    float ibl = bl[c], ibr = br[c], ibo = bo[c] + b2[c];
#pragma unroll
    for (int jp = 0; jp < 4; jp++) {
        a0[jp] = pack2(ibl, ibl);
        a1[jp] = pack2(ibr, ibr);
        a2[jp] = pack2(ibo, ibo);
    }
    for (int kt = 0; kt < 6; kt++) {
        float wl[16], wr[16], wo[16];
        {
            const float4* pl = (const float4*)(g_wt + c * 96 + kt * 16);
            const float4* pr = (const float4*)(g_wt + 9216 + c * 96 + kt * 16);
            const float4* po = (const float4*)(g_wt + 2 * 9216 + c * 96 + kt * 16);
#pragma unroll
            for (int q = 0; q < 4; q++) {
                float4 v = pl[q];
                wl[4 * q] = v.x; wl[4 * q + 1] = v.y; wl[4 * q + 2] = v.z; wl[4 * q + 3] = v.w;
                v = pr[q];
                wr[4 * q] = v.x; wr[4 * q + 1] = v.y; wr[4 * q + 2] = v.z; wr[4 * q + 3] = v.w;
                v = po[q];
                wo[4 * q] = v.x; wo[4 * q + 1] = v.y; wo[4 * q + 2] = v.z; wo[4 * q + 3] = v.w;
            }
        }
        for (int i = tid; i < 512; i += 384) {
            int k = i & 15, r = i >> 4;
            int row = row0 + r;
            float v = (row < n) ? g_acc[row * 96 + kt * 16 + k] : 0.f;
            sh[k * 34 + r] = fmaxf(v, 0.f);   // relu(h1), transposed
        }
        __syncthreads();
#pragma unroll
        for (int k = 0; k < 16; k++) {
            ull wl2 = pack2(wl[k], wl[k]);
            ull wr2 = pack2(wr[k], wr[k]);
            ull wo2 = pack2(wo[k], wo[k]);
#pragma unroll
            for (int jp = 0; jp < 4; jp++) {
                int p = ty + 4 * jp;
                ull h2 = *(const ull*)&sh[k * 34 + 2 * p];
                ffma2(a0[jp], h2, wl2);
                ffma2(a1[jp], h2, wr2);
                ffma2(a2[jp], h2, wo2);
            }
        }
        __syncthreads();
    }
#pragma unroll
    for (int jp = 0; jp < 4; jp++) {
        int p = ty + 4 * jp;
        float2 v0 = unpack2(a0[jp]);
        float2 v1 = unpack2(a1[jp]);
        float2 v2 = unpack2(a2[jp]);
        int ra = row0 + 2 * p, rb = ra + 1;
        if (ra < n) {
            g_hl[ra * 96 + c] = v0.x; g_hr[ra * 96 + c] = v1.x; out[ra * 96 + c] = v2.x;
        }
        if (rb < n) {
            g_hl[rb * 96 + c] = v0.y; g_hr[rb * 96 + c] = v1.y; out[rb * 96 + c] = v2.y;
        }
    }
}

// ---------------- fused GATv2 edge phase: warp per node, 4 edges x 8 lanes ---
// Lane = 8*grp + g. Group grp handles edge (base+grp); lane owns channels
// {4g..4g+3} of each head (float4). Butterfly is 3 levels (xor 4,2,1) and one
// SHFL reduces all 4 edges at once -> ~2.3 SHFL/edge vs 16 in warp-per-edge.
// Cross-group combine of den/ac runs ONCE per node (xor 8,16).
// att pre-scaled by log2(e) so exp(score) == ex2(sum).
// NOTE: internal target (g_acc) resolved in DEVICE code (host symbol != dev ptr).
__global__ void __launch_bounds__(256)
k_gat(const float* __restrict__ att, float* __restrict__ ext_out,
      int use_internal, int n) {
    int v = (blockIdx.x * blockDim.x + threadIdx.x) >> 5;
    int lane = threadIdx.x & 31;
    if (v >= n) return;
    float* out = use_internal ? g_acc : ext_out;
    int grp = lane >> 3, g = lane & 7;
    int beg = g_rs[v], end = g_rs[v + 1];
    const float L2E = 1.44269504088896340736f;

    const float4* attv = (const float4*)att;
    float4 at0 = attv[g], at1 = attv[8 + g], at2 = attv[16 + g];
    at0.x *= L2E; at0.y *= L2E; at0.z *= L2E; at0.w *= L2E;
    at1.x *= L2E; at1.y *= L2E; at1.z *= L2E; at1.w *= L2E;
    at2.x *= L2E; at2.y *= L2E; at2.z *= L2E; at2.w *= L2E;

    const float4* hrv = (const float4*)(g_hr + (size_t)v * 96);
    float4 hr0 = hrv[g], hr1 = hrv[8 + g], hr2 = hrv[16 + g];

    float4 ac0 = make_float4(0.f, 0.f, 0.f, 0.f);
    float4 ac1 = ac0, ac2 = ac0;
    float den0 = 0.f, den1 = 0.f, den2 = 0.f;

#pragma unroll 2
    for (int base = beg; base < end; base += 4) {
        int e = base + grp;
        bool valid = (e < end);
        int ee = valid ? e : end - 1;
        int s = g_ssrc[ee];
        const float4* hlv = (const float4*)(g_hl + (size_t)s * 96);
        float4 h0 = hlv[g], h1 = hlv[8 + g], h2 = hlv[16 + g];

        float s0, s1, s2, t;
        t = h0.x + hr0.x; t = fmaxf(t, NEG * t); s0 = at0.x * t;
        t = h0.y + hr0.y; t = fmaxf(t, NEG * t); s0 = fmaf(at0.y, t, s0);
        t = h0.z + hr0.z; t = fmaxf(t, NEG * t); s0 = fmaf(at0.z, t, s0);
        t = h0.w + hr0.w; t = fmaxf(t, NEG * t); s0 = fmaf(at0.w, t, s0);
        t = h1.x + hr1.x; t = fmaxf(t, NEG * t); s1 = at1.x * t;
        t = h1.y + hr1.y; t = fmaxf(t, NEG * t); s1 = fmaf(at1.y, t, s1);
        t = h1.z + hr1.z; t = fmaxf(t, NEG * t); s1 = fmaf(at1.z, t, s1);
        t = h1.w + hr1.w; t = fmaxf(t, NEG * t); s1 = fmaf(at1.w, t, s1);
        t = h2.x + hr2.x; t = fmaxf(t, NEG * t); s2 = at2.x * t;
        t = h2.y + hr2.y; t = fmaxf(t, NEG * t); s2 = fmaf(at2.y, t, s2);
        t = h2.z + hr2.z; t = fmaxf(t, NEG * t); s2 = fmaf(at2.z, t, s2);
        t = h2.w + hr2.w; t = fmaxf(t, NEG * t); s2 = fmaf(at2.w, t, s2);

#pragma unroll
        for (int o = 4; o; o >>= 1) {           // reduce within 8-lane group
            s0 += __shfl_xor_sync(0xffffffffu, s0, o);
            s1 += __shfl_xor_sync(0xffffffffu, s1, o);
            s2 += __shfl_xor_sync(0xffffffffu, s2, o);
        }
        float p0 = valid ? ex2(s0) : 0.f;
        float p1 = valid ? ex2(s1) : 0.f;
        float p2 = valid ? ex2(s2) : 0.f;
        den0 += p0; den1 += p1; den2 += p2;
        ac0.x = fmaf(p0, h0.x, ac0.x); ac0.y = fmaf(p0, h0.y, ac0.y);
        ac0.z = fmaf(p0, h0.z, ac0.z); ac0.w = fmaf(p0, h0.w, ac0.w);
        ac1.x = fmaf(p1, h1.x, ac1.x); ac1.y = fmaf(p1, h1.y, ac1.y);
        ac1.z = fmaf(p1, h1.z, ac1.z); ac1.w = fmaf(p1, h1.w, ac1.w);
        ac2.x = fmaf(p2, h2.x, ac2.x); ac2.y = fmaf(p2, h2.y, ac2.y);
        ac2.z = fmaf(p2, h2.z, ac2.z); ac2.w = fmaf(p2, h2.w, ac2.w);
    }

    // cross-group combine (once per node): sum over the 4 groups
#pragma unroll
    for (int o = 8; o <= 16; o <<= 1) {
        den0 += __shfl_xor_sync(0xffffffffu, den0, o);
        den1 += __shfl_xor_sync(0xffffffffu, den1, o);
        den2 += __shfl_xor_sync(0xffffffffu, den2, o);
        ac0.x += __shfl_xor_sync(0xffffffffu, ac0.x, o);
        ac0.y += __shfl_xor_sync(0xffffffffu, ac0.y, o);
        ac0.z += __shfl_xor_sync(0xffffffffu, ac0.z, o);
        ac0.w += __shfl_xor_sync(0xffffffffu, ac0.w, o);
        ac1.x += __shfl_xor_sync(0xffffffffu, ac1.x, o);
        ac1.y += __shfl_xor_sync(0xffffffffu, ac1.y, o);
        ac1.z += __shfl_xor_sync(0xffffffffu, ac1.z, o);
        ac1.w += __shfl_xor_sync(0xffffffffu, ac1.w, o);
        ac2.x += __shfl_xor_sync(0xffffffffu, ac2.x, o);
        ac2.y += __shfl_xor_sync(0xffffffffu, ac2.y, o);
        ac2.z += __shfl_xor_sync(0xffffffffu, ac2.z, o);
        ac2.w += __shfl_xor_sync(0xffffffffu, ac2.w, o);
    }

    if (grp == 0) {
        float r0 = __fdividef(1.f, den0 + 1e-16f);
        float r1 = __fdividef(1.f, den1 + 1e-16f);
        float r2 = __fdividef(1.f, den2 + 1e-16f);
        float4* orow = (float4*)(out + (size_t)v * 96);
        float4 o0 = orow[g], o1 = orow[8 + g], o2 = orow[16 + g];
        o0.x = fmaf(ac0.x, r0, o0.x); o0.y = fmaf(ac0.y, r0, o0.y);
        o0.z = fmaf(ac0.z, r0, o0.z); o0.w = fmaf(ac0.w, r0, o0.w);
        o1.x = fmaf(ac1.x, r1, o1.x); o1.y = fmaf(ac1.y, r1, o1.y);
        o1.z = fmaf(ac1.z, r1, o1.z); o1.w = fmaf(ac1.w, r1, o1.w);
        o2.x = fmaf(ac2.x, r2, o2.x); o2.y = fmaf(ac2.y, r2, o2.y);
        o2.z = fmaf(ac2.z, r2, o2.z); o2.w = fmaf(ac2.w, r2, o2.w);
        orow[g] = o0; orow[8 + g] = o1; orow[16 + g] = o2;
    }
}

// ---------------- launch ------------------------------------------------------

extern "C" void kernel_launch(void* const* d_in, const int* in_sizes, int n_in,
                              void* d_out, int out_size) {
    const float* x     = (const float*)d_in[0];
    const void*  ei    = (const void*)d_in[1];
    const float* W0    = (const float*)d_in[2];
    const float* Wl1   = (const float*)d_in[3];
    const float* bl1   = (const float*)d_in[4];
    const float* Wr1   = (const float*)d_in[5];
    const float* br1   = (const float*)d_in[6];
    const float* att1  = (const float*)d_in[7];
    const float* b1    = (const float*)d_in[8];
    const float* Wf    = (const float*)d_in[9];
    const float* bf    = (const float*)d_in[10];
    const float* Wl2   = (const float*)d_in[11];
    const float* bl2   = (const float*)d_in[12];
    const float* Wr2   = (const float*)d_in[13];
    const float* br2   = (const float*)d_in[14];
    const float* att2  = (const float*)d_in[15];
    const float* b2    = (const float*)d_in[16];
    const float* Wlast = (const float*)d_in[17];
    const float* blast = (const float*)d_in[18];
    float* out = (float*)d_out;

    int n = in_sizes[0] / 128;
    int E = in_sizes[1] / 2;
    int NB = (n + 1023) / 1024;          // scan blocks (<=128)

    // ---- CSR build (by destination) + weight transpose ----
    k_init<<<(n + 255) / 256, 256>>>((const int*)ei, n);
    k_wt<<<(9216 + 255) / 256, 256>>>(Wl2, Wr2, Wlast);
    k_edges<<<(E + 255) / 256, 256>>>(ei, E);
    k_scan1<<<NB, 1024>>>(n);
    k_scan2<<<1, 128>>>(NB);
    k_scan3<<<(n + 255) / 256, 256>>>(n, E);
    k_scatter<<<(E + 255) / 256, 256>>>(E);

    // ---- node transforms ----
    k_lin0<<<(n + 15) / 16, 256>>>(x, W0, n);
    k_node1<<<(n + 63) / 64, dim3(96, 4)>>>(Wl1, bl1, Wr1, br1, Wf, bf, b1, n);

    // ---- layer 1 edge phase (into g_acc which holds skip + b1) ----
    k_gat<<<(n + 7) / 8, 256>>>(att1, out, 1, n);

    // ---- layer 2 node transforms (relu fused on load; out gets skip + b2) ----
    k_node2<<<(n + 31) / 32, dim3(96, 4)>>>(bl2, br2, blast, b2, out, n);

    // ---- layer 2 edge phase (into d_out) ----
    k_gat<<<(n + 7) / 8, 256>>>(att2, out, 0, n);
}

// round 10
// speedup vs baseline: 1.3685x; 1.3685x over previous
#include <cuda_runtime.h>

#define MAXN 100000
#define MAXE 1600000
#define NEG 0.2f

typedef unsigned long long ull;

// ---------------- scratch (static device globals; no allocation) -------------
__device__ float g_h0 [MAXN * 16];    // relu(x@W0)
__device__ float g_hl [MAXN * 96];    // source transform (current layer)
__device__ float g_hr [MAXN * 96];    // target transform (current layer)
__device__ float g_acc[MAXN * 96];    // layer-1 accumulator = skip + b1 + msgs
__device__ int   g_src[MAXE];
__device__ int   g_dst[MAXE];
__device__ int   g_ssrc[MAXE];        // src ids sorted by dst (CSR payload)
__device__ int   g_cnt[MAXN];         // in-degree histogram
__device__ int   g_rs [MAXN + 1];     // CSR row starts
__device__ int   g_cur[MAXN];         // scatter cursors
__device__ int   g_bsum[128];
__device__ int   g_boff[128];
__device__ int   g_is64;

// ---------------- asm helpers -------------------------------------------------
__device__ __forceinline__ void ffma2(ull& acc, ull a, ull b) {
    asm("fma.rn.f32x2 %0, %1, %2, %0;" : "+l"(acc) : "l"(a), "l"(b));
}
__device__ __forceinline__ ull pack2(float x, float y) {
    ull r; asm("mov.b64 %0, {%1, %2};" : "=l"(r) : "f"(x), "f"(y)); return r;
}
__device__ __forceinline__ float2 unpack2(ull v) {
    float2 r; asm("mov.b64 {%0, %1}, %2;" : "=f"(r.x), "=f"(r.y) : "l"(v)); return r;
}
__device__ __forceinline__ float ex2(float v) {
    float r; asm("ex2.approx.ftz.f32 %0, %1;" : "=f"(r) : "f"(v)); return r;
}

// ---------------- init: zero histogram + dtype detect -------------------------
// Detect int64 vs int32 edge_index: node ids < 2^17, so int64 => odd words 0.
__global__ void k_init(const int* __restrict__ p, int n) {
    int i = blockIdx.x * blockDim.x + threadIdx.x;
    if (i < n) g_cnt[i] = 0;
    if (i == 0) {
        int acc = 0;
#pragma unroll
        for (int j = 1; j < 64; j += 2) acc |= p[j];
        g_is64 = (acc == 0) ? 1 : 0;
    }
}

__global__ void k_edges(const void* __restrict__ ei, int E) {
    int i = blockIdx.x * blockDim.x + threadIdx.x;
    if (i >= E) return;
    int s, d;
    if (g_is64) {
        const long long* p = (const long long*)ei;
        s = (int)p[i]; d = (int)p[E + i];
    } else {
        const int* p = (const int*)ei;
        s = p[i]; d = p[E + i];
    }
    g_src[i] = s;
    g_dst[i] = d;
    atomicAdd(&g_cnt[d], 1);
}

// ---------------- scan (3-kernel exclusive prefix sum over g_cnt) ------------

__global__ void k_scan1(int n) {
    __shared__ int tmp[1024];
    int tid = threadIdx.x;
    int i = blockIdx.x * 1024 + tid;
    int v = (i < n) ? g_cnt[i] : 0;
    tmp[tid] = v;
    __syncthreads();
#pragma unroll
    for (int o = 1; o < 1024; o <<= 1) {
        int t = (tid >= o) ? tmp[tid - o] : 0;
        __syncthreads();
        tmp[tid] += t;
        __syncthreads();
    }
    if (i < n) g_rs[i] = tmp[tid] - v;         // block-local exclusive
    if (tid == 1023) g_bsum[blockIdx.x] = tmp[tid];
}

__global__ void k_scan2(int nb) {
    __shared__ int tmp[128];
    int tid = threadIdx.x;
    int v = (tid < nb) ? g_bsum[tid] : 0;
    tmp[tid] = v;
    __syncthreads();
#pragma unroll
    for (int o = 1; o < 128; o <<= 1) {
        int t = (tid >= o) ? tmp[tid - o] : 0;
        __syncthreads();
        tmp[tid] += t;
        __syncthreads();
    }
    if (tid < nb) g_boff[tid] = tmp[tid] - v;  // exclusive block offsets
}

__global__ void k_scan3(int n, int E) {
    int i = blockIdx.x * blockDim.x + threadIdx.x;
    if (i < n) {
        int r = g_rs[i] + g_boff[i >> 10];
        g_rs[i] = r;
        g_cur[i] = r;
    }
    if (i == 0) g_rs[n] = E;
}

__global__ void k_scatter(int E) {
    int i = blockIdx.x * blockDim.x + threadIdx.x;
    if (i >= E) return;
    int d = g_dst[i];
    int pos = atomicAdd(&g_cur[d], 1);
    g_ssrc[pos] = g_src[i];
}

// ---------------- node transforms --------------------------------------------

// h0 = relu(x @ W0) : [n,128]@[128,16]. Shared-staged, float4 global loads.
__global__ void __launch_bounds__(256)
k_lin0(const float* __restrict__ x, const float* __restrict__ W0, int n) {
    __shared__ float sx[16 * 128];   // 16 rows of x
    __shared__ float sw[128 * 16];   // W0
    int tid = threadIdx.x;
    int row0 = blockIdx.x * 16;
    for (int i = tid; i < 512; i += 256)
        ((float4*)sw)[i] = ((const float4*)W0)[i];
    for (int i = tid; i < 512; i += 256) {
        int r = i >> 5;                // row within tile
        int row = row0 + r;
        float4 v = make_float4(0.f, 0.f, 0.f, 0.f);
        if (row < n) v = ((const float4*)x)[row * 32 + (i & 31)];
        ((float4*)sx)[i] = v;
    }
    __syncthreads();
    int r = tid >> 4, c = tid & 15;
    const float4* sxr = (const float4*)(sx + r * 128);
    float acc = 0.f;
#pragma unroll
    for (int k4 = 0; k4 < 32; k4++) {
        float4 h = sxr[k4];
        acc = fmaf(h.x, sw[(4 * k4 + 0) * 16 + c], acc);
        acc = fmaf(h.y, sw[(4 * k4 + 1) * 16 + c], acc);
        acc = fmaf(h.z, sw[(4 * k4 + 2) * 16 + c], acc);
        acc = fmaf(h.w, sw[(4 * k4 + 3) * 16 + c], acc);
    }
    int row = row0 + r;
    if (row < n) g_h0[row * 16 + c] = fmaxf(acc, 0.f);
}

// layer-1 transforms: weights in registers (one output column per thread),
// h rows staged in shared (broadcast reads). 64 rows per block.
// Weight loads Wl[k*96+c]: consecutive c across lanes => fully coalesced.
__global__ void __launch_bounds__(384)
k_node1(const float* __restrict__ Wl, const float* __restrict__ bl,
        const float* __restrict__ Wr, const float* __restrict__ br,
        const float* __restrict__ Wf, const float* __restrict__ bf,
        const float* __restrict__ b1, int n) {
    __shared__ float sh[64 * 16];
    int c = threadIdx.x, ty = threadIdx.y;
    int tid = ty * 96 + c;
    int row0 = blockIdx.x * 64;
    float wl[16], wr[16], wf[16];
#pragma unroll
    for (int k = 0; k < 16; k++) {
        wl[k] = Wl[k * 96 + c];
        wr[k] = Wr[k * 96 + c];
        wf[k] = Wf[k * 96 + c];
    }
    float cbl = bl[c], cbr = br[c], cbf = bf[c] + b1[c];
    for (int i = tid; i < 1024; i += 384) {
        int r = i >> 4, k = i & 15;
        int row = row0 + r;
        sh[i] = (row < n) ? g_h0[row * 16 + k] : 0.f;
    }
    __syncthreads();
    for (int r = ty; r < 64; r += 4) {
        int row = row0 + r;
        if (row >= n) continue;
        float a0 = cbl, a1 = cbr, a2 = cbf;
#pragma unroll
        for (int k = 0; k < 16; k++) {
            float h = sh[r * 16 + k];
            a0 = fmaf(h, wl[k], a0);
            a1 = fmaf(h, wr[k], a1);
            a2 = fmaf(h, wf[k], a2);
        }
        g_hl[row * 96 + c] = a0;
        g_hr[row * 96 + c] = a1;
        g_acc[row * 96 + c] = a2;
    }
}

// layer-2 transforms via packed f32x2 FMA (FFMA2): rows in pairs, K=96 in 6
// chunks. Weights loaded DIRECT from W (consecutive c across lanes = coalesced
// 128B lines — the g_wt float4 "fix" of R8/R9 made each lane stride 384B and
// split every warp load into 32 sectors; reverted).
// sh transposed [k][r] stride 34 (aligned LDS.64, conflict-free).
__global__ void __launch_bounds__(384, 1)
k_node2(const float* __restrict__ Wl, const float* __restrict__ bl,
        const float* __restrict__ Wr, const float* __restrict__ br,
        const float* __restrict__ Wo, const float* __restrict__ bo,
        const float* __restrict__ b2, float* __restrict__ out, int n) {
    __shared__ float sh[16 * 34];
    int c = threadIdx.x, ty = threadIdx.y;
    int tid = ty * 96 + c;
    int row0 = blockIdx.x * 32;
    ull a0[4], a1[4], a2[4];
    float ibl = bl[c], ibr = br[c], ibo = bo[c] + b2[c];
#pragma unroll
    for (int jp = 0; jp < 4; jp++) {
        a0[jp] = pack2(ibl, ibl);
        a1[jp] = pack2(ibr, ibr);
        a2[jp] = pack2(ibo, ibo);
    }
    for (int kt = 0; kt < 6; kt++) {
        float wl[16], wr[16], wo[16];
#pragma unroll
        for (int k = 0; k < 16; k++) {
            wl[k] = Wl[(kt * 16 + k) * 96 + c];
            wr[k] = Wr[(kt * 16 + k) * 96 + c];
            wo[k] = Wo[(kt * 16 + k) * 96 + c];
        }
        for (int i = tid; i < 512; i += 384) {
            int k = i & 15, r = i >> 4;
            int row = row0 + r;
            float v = (row < n) ? g_acc[row * 96 + kt * 16 + k] : 0.f;
            sh[k * 34 + r] = fmaxf(v, 0.f);   // relu(h1), transposed
        }
        __syncthreads();
#pragma unroll
        for (int k = 0; k < 16; k++) {
            ull wl2 = pack2(wl[k], wl[k]);
            ull wr2 = pack2(wr[k], wr[k]);
            ull wo2 = pack2(wo[k], wo[k]);
#pragma unroll
            for (int jp = 0; jp < 4; jp++) {
                int p = ty + 4 * jp;
                ull h2 = *(const ull*)&sh[k * 34 + 2 * p];
                ffma2(a0[jp], h2, wl2);
                ffma2(a1[jp], h2, wr2);
                ffma2(a2[jp], h2, wo2);
            }
        }
        __syncthreads();
    }
#pragma unroll
    for (int jp = 0; jp < 4; jp++) {
        int p = ty + 4 * jp;
        float2 v0 = unpack2(a0[jp]);
        float2 v1 = unpack2(a1[jp]);
        float2 v2 = unpack2(a2[jp]);
        int ra = row0 + 2 * p, rb = ra + 1;
        if (ra < n) {
            g_hl[ra * 96 + c] = v0.x; g_hr[ra * 96 + c] = v1.x; out[ra * 96 + c] = v2.x;
        }
        if (rb < n) {
            g_hl[rb * 96 + c] = v0.y; g_hr[rb * 96 + c] = v1.y; out[rb * 96 + c] = v2.y;
        }
    }
}

// ---------------- fused GATv2 edge phase: warp per node, 4 edges x 8 lanes ---
// Lane = 8*grp + g. Group grp handles edge (base+grp); lane owns channels
// {4g..4g+3} of each head (float4). One SHFL reduces all 4 edges at once.
// Cross-group combine of den/ac runs ONCE per node (xor 8,16).
// att pre-scaled by log2(e) so exp(score) == ex2(sum).
// NOTE: internal target (g_acc) resolved in DEVICE code (host symbol != dev ptr).
__global__ void __launch_bounds__(256)
k_gat(const float* __restrict__ att, float* __restrict__ ext_out,
      int use_internal, int n) {
    int v = (blockIdx.x * blockDim.x + threadIdx.x) >> 5;
    int lane = threadIdx.x & 31;
    if (v >= n) return;
    float* out = use_internal ? g_acc : ext_out;
    int grp = lane >> 3, g = lane & 7;
    int beg = g_rs[v], end = g_rs[v + 1];
    const float L2E = 1.44269504088896340736f;

    const float4* attv = (const float4*)att;
    float4 at0 = attv[g], at1 = attv[8 + g], at2 = attv[16 + g];
    at0.x *= L2E; at0.y *= L2E; at0.z *= L2E; at0.w *= L2E;
    at1.x *= L2E; at1.y *= L2E; at1.z *= L2E; at1.w *= L2E;
    at2.x *= L2E; at2.y *= L2E; at2.z *= L2E; at2.w *= L2E;

    const float4* hrv = (const float4*)(g_hr + (size_t)v * 96);
    float4 hr0 = hrv[g], hr1 = hrv[8 + g], hr2 = hrv[16 + g];

    float4 ac0 = make_float4(0.f, 0.f, 0.f, 0.f);
    float4 ac1 = ac0, ac2 = ac0;
    float den0 = 0.f, den1 = 0.f, den2 = 0.f;

#pragma unroll 2
    for (int base = beg; base < end; base += 4) {
        int e = base + grp;
        bool valid = (e < end);
        int ee = valid ? e : end - 1;
        int s = g_ssrc[ee];
        const float4* hlv = (const float4*)(g_hl + (size_t)s * 96);
        float4 h0 = hlv[g], h1 = hlv[8 + g], h2 = hlv[16 + g];

        float s0, s1, s2, t;
        t = h0.x + hr0.x; t = fmaxf(t, NEG * t); s0 = at0.x * t;
        t = h0.y + hr0.y; t = fmaxf(t, NEG * t); s0 = fmaf(at0.y, t, s0);
        t = h0.z + hr0.z; t = fmaxf(t, NEG * t); s0 = fmaf(at0.z, t, s0);
        t = h0.w + hr0.w; t = fmaxf(t, NEG * t); s0 = fmaf(at0.w, t, s0);
        t = h1.x + hr1.x; t = fmaxf(t, NEG * t); s1 = at1.x * t;
        t = h1.y + hr1.y; t = fmaxf(t, NEG * t); s1 = fmaf(at1.y, t, s1);
        t = h1.z + hr1.z; t = fmaxf(t, NEG * t); s1 = fmaf(at1.z, t, s1);
        t = h1.w + hr1.w; t = fmaxf(t, NEG * t); s1 = fmaf(at1.w, t, s1);
        t = h2.x + hr2.x; t = fmaxf(t, NEG * t); s2 = at2.x * t;
        t = h2.y + hr2.y; t = fmaxf(t, NEG * t); s2 = fmaf(at2.y, t, s2);
        t = h2.z + hr2.z; t = fmaxf(t, NEG * t); s2 = fmaf(at2.z, t, s2);
        t = h2.w + hr2.w; t = fmaxf(t, NEG * t); s2 = fmaf(at2.w, t, s2);

#pragma unroll
        for (int o = 4; o; o >>= 1) {           // reduce within 8-lane group
            s0 += __shfl_xor_sync(0xffffffffu, s0, o);
            s1 += __shfl_xor_sync(0xffffffffu, s1, o);
            s2 += __shfl_xor_sync(0xffffffffu, s2, o);
        }
        float p0 = valid ? ex2(s0) : 0.f;
        float p1 = valid ? ex2(s1) : 0.f;
        float p2 = valid ? ex2(s2) : 0.f;
        den0 += p0; den1 += p1; den2 += p2;
        ac0.x = fmaf(p0, h0.x, ac0.x); ac0.y = fmaf(p0, h0.y, ac0.y);
        ac0.z = fmaf(p0, h0.z, ac0.z); ac0.w = fmaf(p0, h0.w, ac0.w);
        ac1.x = fmaf(p1, h1.x, ac1.x); ac1.y = fmaf(p1, h1.y, ac1.y);
        ac1.z = fmaf(p1, h1.z, ac1.z); ac1.w = fmaf(p1, h1.w, ac1.w);
        ac2.x = fmaf(p2, h2.x, ac2.x); ac2.y = fmaf(p2, h2.y, ac2.y);
        ac2.z = fmaf(p2, h2.z, ac2.z); ac2.w = fmaf(p2, h2.w, ac2.w);
    }

    // cross-group combine (once per node): sum over the 4 groups
#pragma unroll
    for (int o = 8; o <= 16; o <<= 1) {
        den0 += __shfl_xor_sync(0xffffffffu, den0, o);
        den1 += __shfl_xor_sync(0xffffffffu, den1, o);
        den2 += __shfl_xor_sync(0xffffffffu, den2, o);
        ac0.x += __shfl_xor_sync(0xffffffffu, ac0.x, o);
        ac0.y += __shfl_xor_sync(0xffffffffu, ac0.y, o);
        ac0.z += __shfl_xor_sync(0xffffffffu, ac0.z, o);
        ac0.w += __shfl_xor_sync(0xffffffffu, ac0.w, o);
        ac1.x += __shfl_xor_sync(0xffffffffu, ac1.x, o);
        ac1.y += __shfl_xor_sync(0xffffffffu, ac1.y, o);
        ac1.z += __shfl_xor_sync(0xffffffffu, ac1.z, o);
        ac1.w += __shfl_xor_sync(0xffffffffu, ac1.w, o);
        ac2.x += __shfl_xor_sync(0xffffffffu, ac2.x, o);
        ac2.y += __shfl_xor_sync(0xffffffffu, ac2.y, o);
        ac2.z += __shfl_xor_sync(0xffffffffu, ac2.z, o);
        ac2.w += __shfl_xor_sync(0xffffffffu, ac2.w, o);
    }

    if (grp == 0) {
        float r0 = __fdividef(1.f, den0 + 1e-16f);
        float r1 = __fdividef(1.f, den1 + 1e-16f);
        float r2 = __fdividef(1.f, den2 + 1e-16f);
        float4* orow = (float4*)(out + (size_t)v * 96);
        float4 o0 = orow[g], o1 = orow[8 + g], o2 = orow[16 + g];
        o0.x = fmaf(ac0.x, r0, o0.x); o0.y = fmaf(ac0.y, r0, o0.y);
        o0.z = fmaf(ac0.z, r0, o0.z); o0.w = fmaf(ac0.w, r0, o0.w);
        o1.x = fmaf(ac1.x, r1, o1.x); o1.y = fmaf(ac1.y, r1, o1.y);
        o1.z = fmaf(ac1.z, r1, o1.z); o1.w = fmaf(ac1.w, r1, o1.w);
        o2.x = fmaf(ac2.x, r2, o2.x); o2.y = fmaf(ac2.y, r2, o2.y);
        o2.z = fmaf(ac2.z, r2, o2.z); o2.w = fmaf(ac2.w, r2, o2.w);
        orow[g] = o0; orow[8 + g] = o1; orow[16 + g] = o2;
    }
}

// ---------------- launch ------------------------------------------------------

extern "C" void kernel_launch(void* const* d_in, const int* in_sizes, int n_in,
                              void* d_out, int out_size) {
    const float* x     = (const float*)d_in[0];
    const void*  ei    = (const void*)d_in[1];
    const float* W0    = (const float*)d_in[2];
    const float* Wl1   = (const float*)d_in[3];
    const float* bl1   = (const float*)d_in[4];
    const float* Wr1   = (const float*)d_in[5];
    const float* br1   = (const float*)d_in[6];
    const float* att1  = (const float*)d_in[7];
    const float* b1    = (const float*)d_in[8];
    const float* Wf    = (const float*)d_in[9];
    const float* bf    = (const float*)d_in[10];
    const float* Wl2   = (const float*)d_in[11];
    const float* bl2   = (const float*)d_in[12];
    const float* Wr2   = (const float*)d_in[13];
    const float* br2   = (const float*)d_in[14];
    const float* att2  = (const float*)d_in[15];
    const float* b2    = (const float*)d_in[16];
    const float* Wlast = (const float*)d_in[17];
    const float* blast = (const float*)d_in[18];
    float* out = (float*)d_out;

    int n = in_sizes[0] / 128;
    int E = in_sizes[1] / 2;
    int NB = (n + 1023) / 1024;          // scan blocks (<=128)

    // Launch order puts k_node1 at index 3 — that's the slot ncu samples,
    // so we finally profile a node GEMM instead of k_scan1. (lin0/node1 have
    // no dependency on the CSR build.)
    k_init<<<(n + 255) / 256, 256>>>((const int*)ei, n);
    k_edges<<<(E + 255) / 256, 256>>>(ei, E);
    k_lin0<<<(n + 15) / 16, 256>>>(x, W0, n);
    k_node1<<<(n + 63) / 64, dim3(96, 4)>>>(Wl1, bl1, Wr1, br1, Wf, bf, b1, n);
    k_scan1<<<NB, 1024>>>(n);
    k_scan2<<<1, 128>>>(NB);
    k_scan3<<<(n + 255) / 256, 256>>>(n, E);
    k_scatter<<<(E + 255) / 256, 256>>>(E);

    // ---- layer 1 edge phase (into g_acc which holds skip + b1) ----
    k_gat<<<(n + 7) / 8, 256>>>(att1, out, 1, n);

    // ---- layer 2 node transforms (relu fused on load; out gets skip + b2) ----
    k_node2<<<(n + 31) / 32, dim3(96, 4)>>>(Wl2, bl2, Wr2, br2, Wlast, blast, b2, out, n);

    // ---- layer 2 edge phase (into d_out) ----
    k_gat<<<(n + 7) / 8, 256>>>(att2, out, 0, n);
}